// round 8
// baseline (speedup 1.0000x reference)
#include <cuda_runtime.h>

#define SB 2048
#define TB 64
#define NB 256

typedef unsigned long long ull;

__device__ float g_part[NB];

static __device__ __forceinline__ ull pk2(float a, float b) {
    ull r; asm("mov.b64 %0,{%1,%2};" : "=l"(r) : "f"(a), "f"(b)); return r;
}
static __device__ __forceinline__ void upk2(ull v, float& a, float& b) {
    asm("mov.b64 {%0,%1},%2;" : "=f"(a), "=f"(b) : "l"(v));
}
static __device__ __forceinline__ ull fma2(ull a, ull b, ull c) {
    ull d; asm("fma.rn.f32x2 %0,%1,%2,%3;" : "=l"(d) : "l"(a), "l"(b), "l"(c)); return d;
}
static __device__ __forceinline__ ull add2(ull a, ull b) {
    ull d; asm("add.rn.f32x2 %0,%1,%2;" : "=l"(d) : "l"(a), "l"(b)); return d;
}

__global__ __launch_bounds__(64, 8) void crf_batch_kernel(
    const float* __restrict__ emis,     // (B, S, T)
    const float* __restrict__ startT,   // (T)
    const float* __restrict__ endT,     // (T)
    const float* __restrict__ trans,    // (T, T)
    const int*   __restrict__ tags,     // (B, S)
    const int*   __restrict__ maskp)    // (B, S)
{
    const int j = threadIdx.x;          // owned next-state, 0..63
    const int b = blockIdx.x;
    const float* __restrict__ em = emis + (size_t)b * SB * TB;
    const int*   __restrict__ tg = tags  + b * SB;
    const int*   __restrict__ mk = maskp + b * SB;

    __shared__ __align__(16) float p[2][TB];   // exp-domain alpha, double-buffered
    __shared__ float craw[2];                   // thread 0's raw dot sum (normalizer seed)
    __shared__ float nred[2];                   // numerator partials per warp
    __shared__ int   mred[2];                   // mask-sum partials per warp
    __shared__ float red[2];                    // final end-term reduction

    // ---------------- numerator: gold tag path (parallel over steps) ----------------
    float nacc = 0.f;
    int   macc = 0;
    for (int t = j; t < SB; t += TB) {
        int m = mk[t];
        macc += m;
        if (t > 0 && m) {
            int tp = tg[t - 1], tc = tg[t];
            nacc += trans[tp * TB + tc] + em[t * TB + tc];
        }
    }
    if (j == 0) nacc += startT[tg[0]] + em[tg[0]];
    #pragma unroll
    for (int o = 16; o; o >>= 1) {
        nacc += __shfl_down_sync(0xffffffffu, nacc, o);
        macc += __shfl_down_sync(0xffffffffu, macc, o);
    }
    if ((j & 31) == 0) { nred[j >> 5] = nacc; mred[j >> 5] = macc; }

    // ---------------- load exp(transitions) column j into registers ----------------
    ull Ecol[TB / 2];
    #pragma unroll
    for (int i = 0; i < TB / 2; i++) {
        float e0 = expf(trans[(2 * i) * TB + j]);
        float e1 = expf(trans[(2 * i + 1) * TB + j]);
        Ecol[i] = pk2(e0, e1);
    }

    // ---------------- init: alpha0 = startT + em[0]; p = exp(alpha0), M = 0 --------
    p[0][j] = expf(startT[j] + em[j]);
    if (j == 0) craw[0] = 1.0f;

    // prefetch ring for emissions + mask (distance 4)
    float emr[4];
    int   mkr[4];
    #pragma unroll
    for (int k = 0; k < 4; k++) {
        int t = 1 + k;
        emr[k] = (t < SB) ? em[t * TB + j] : 0.f;
        mkr[k] = (t < SB) ? mk[t] : 0;
    }

    double Mtot = 0.0;   // running log-offset; double to avoid 2047-term fp32 drift

    // ---------------- forward recursion: one barrier per step ----------------
    #pragma unroll 1
    for (int tb = 1; tb < SB; tb += 4) {
        #pragma unroll
        for (int k = 0; k < 4; k++) {
            const int t = tb + k;
            if (t >= SB) break;
            const int rb = k & 1;        // read buffer parity ((t-1)&1, tb odd)
            const int wb = rb ^ 1;       // write buffer

            __syncthreads();
            float c = __logf(craw[rb]);

            // dot: s_j = sum_i p[i] * E[i][j]   (16x LDS.128 broadcast, 32x FFMA2)
            const ulonglong2* __restrict__ pv = (const ulonglong2*)p[rb];
            ull a0 = 0ull, a1 = 0ull, a2 = 0ull, a3 = 0ull;
            #pragma unroll
            for (int i = 0; i < 16; i += 4) {
                ulonglong2 v0 = pv[i + 0];
                a0 = fma2(v0.x, Ecol[2 * i + 0], a0);
                a1 = fma2(v0.y, Ecol[2 * i + 1], a1);
                ulonglong2 v1 = pv[i + 1];
                a2 = fma2(v1.x, Ecol[2 * i + 2], a2);
                a3 = fma2(v1.y, Ecol[2 * i + 3], a3);
                ulonglong2 v2 = pv[i + 2];
                a0 = fma2(v2.x, Ecol[2 * i + 4], a0);
                a1 = fma2(v2.y, Ecol[2 * i + 5], a1);
                ulonglong2 v3 = pv[i + 3];
                a2 = fma2(v3.x, Ecol[2 * i + 6], a2);
                a3 = fma2(v3.y, Ecol[2 * i + 7], a3);
            }
            ull sa = add2(add2(a0, a1), add2(a2, a3));
            float s0, s1; upk2(sa, s0, s1);
            float s = s0 + s1;

            float q;
            if (mkr[k]) {
                q = s * __expf(emr[k] - c);   // alpha'_j = M + c + log q
                Mtot += (double)c;
            } else {
                q = p[rb][j];                 // alpha unchanged
            }
            p[wb][j] = q;
            if (j == 0) craw[wb] = s;         // next step's normalizer seed

            // prefetch t+4
            if (t + 4 < SB) {
                emr[k] = em[(t + 4) * TB + j];
                mkr[k] = mk[t + 4];
            }
        }
    }

    // ---------------- finish: den = M + log(sum_j p_j * exp(endT_j)) ----------------
    __syncthreads();
    // final write buffer after t=2047: ((2047-1)&1)^1 = 1
    float term = p[1][j] * __expf(endT[j]);
    #pragma unroll
    for (int o = 16; o; o >>= 1)
        term += __shfl_down_sync(0xffffffffu, term, o);
    if ((j & 31) == 0) red[j >> 5] = term;
    __syncthreads();

    if (j == 0) {
        float total = red[0] + red[1];
        float den = (float)(Mtot + (double)logf(total));
        float num = nred[0] + nred[1];
        int   se  = mred[0] + mred[1] - 1;    // seq_end index
        num += endT[tg[se]];
        g_part[b] = den - num;
    }
}

__global__ void crf_reduce_kernel(float* __restrict__ out) {
    int t = threadIdx.x;
    float v = g_part[t];
    #pragma unroll
    for (int o = 16; o; o >>= 1)
        v += __shfl_down_sync(0xffffffffu, v, o);
    __shared__ float sh[8];
    if ((t & 31) == 0) sh[t >> 5] = v;
    __syncthreads();
    if (t == 0) {
        float s = 0.f;
        #pragma unroll
        for (int i = 0; i < 8; i++) s += sh[i];
        out[0] = s / (float)NB;    // mean(den - num) = -(mean(num - den))
    }
}

extern "C" void kernel_launch(void* const* d_in, const int* in_sizes, int n_in,
                              void* d_out, int out_size) {
    const float* emissions = (const float*)d_in[0];
    const float* startT    = (const float*)d_in[1];
    const float* endT      = (const float*)d_in[2];
    const float* trans     = (const float*)d_in[3];
    const int*   tags      = (const int*)d_in[4];
    const int*   mask      = (const int*)d_in[5];
    (void)in_sizes; (void)n_in; (void)out_size;

    crf_batch_kernel<<<NB, TB>>>(emissions, startT, endT, trans, tags, mask);
    crf_reduce_kernel<<<1, NB>>>((float*)d_out);
}